// round 4
// baseline (speedup 1.0000x reference)
#include <cuda_runtime.h>

// PatchMerging fused: octant gather -> LayerNorm(768) (folded) -> GEMM 768x192 -> transposed store
// x: (2, 96, 32, 64, 64) f32 ; gamma,beta: (768,) ; w_red: (768, 192)
// out: (2, 192, 16, 32, 32) f32
//
// LN fold: out[t,o] = rstd_t * (sum_k y[t,k]*(gamma_k*W[k,o])) - rstd_t*mu_t*g[o] + c[o]
//   g[o] = sum_k gamma_k W[k,o],  c[o] = sum_k beta_k W[k,o]
// so a single pass over x suffices (stats accumulated during gather).

#define KTOT 768
#define NOUT 192
#define TM   128
#define KT   32
#define NKT  24   // 768/32

// x strides (floats)
#define XS_C 131072     // 32*64*64
#define XS_D 4096       // 64*64
#define XS_H 64
#define XS_B 12582912   // 96*131072
// out strides (floats)
#define OS_O 16384      // 16*32*32
#define OS_B 3145728    // 192*16384
#define OS_D 1024
#define OS_H 32

__device__ float g_gv[NOUT];
__device__ float g_cv[NOUT];

__global__ void prep_kernel(const float* __restrict__ w,
                            const float* __restrict__ gamma,
                            const float* __restrict__ beta) {
    int o = threadIdx.x;
    if (o < NOUT) {
        float g = 0.f, c = 0.f;
#pragma unroll 8
        for (int k = 0; k < KTOT; ++k) {
            float wv = w[k * NOUT + o];
            g += gamma[k] * wv;
            c += beta[k] * wv;
        }
        g_gv[o] = g;
        g_cv[o] = c;
    }
}

__device__ __forceinline__ unsigned long long pack2(float lo, float hi) {
    unsigned long long r;
    asm("mov.b64 %0, {%1, %2};" : "=l"(r) : "f"(lo), "f"(hi));
    return r;
}
__device__ __forceinline__ void ffma2(unsigned long long& d,
                                      unsigned long long a,
                                      unsigned long long b) {
    asm("fma.rn.f32x2 %0, %1, %2, %0;" : "+l"(d) : "l"(a), "l"(b));
}
__device__ __forceinline__ float2 unpack2(unsigned long long v) {
    float2 r;
    asm("mov.b64 {%0, %1}, %2;" : "=f"(r.x), "=f"(r.y) : "l"(v));
    return r;
}

__global__ __launch_bounds__(256, 1)
void pm_kernel(const float* __restrict__ x,
               const float* __restrict__ gamma,
               const float* __restrict__ w,
               float* __restrict__ out) {
    __shared__ float A_s[KT][TM];        // 16 KB  raw y tile (k-major x token)
    __shared__ float B_s[KT][NOUT];      // 24 KB  gamma-scaled W tile
    __shared__ float gs[KTOT];           // 3 KB
    __shared__ float mu_s[TM];
    __shared__ float rs_s[TM];

    const int tid = threadIdx.x;
    const int T0  = blockIdx.x * TM;
    const int tl  = tid & (TM - 1);
    const int kk0 = tid >> 7;            // 0/1: which k-parity this thread gathers

    // preload gamma (768 values, 3 per thread)
    gs[tid]       = gamma[tid];
    gs[tid + 256] = gamma[tid + 256];
    gs[tid + 512] = gamma[tid + 512];

    // token coords for this thread's gather lane
    const int t  = T0 + tl;
    const int wx = t & 31;
    const int hy = (t >> 5) & 31;
    const int dz = (t >> 10) & 15;
    const int bb = t >> 14;
    const int xbase = bb * XS_B + (2 * dz) * XS_D + (2 * hy) * XS_H + 2 * wx;

    // accumulators: 8 rows x 12 cols = 48 f32x2
    unsigned long long acc[8][6];
#pragma unroll
    for (int r = 0; r < 8; ++r)
#pragma unroll
        for (int j = 0; j < 6; ++j) acc[r][j] = 0ull;

    float sum = 0.f, sq = 0.f;
    const int rt = tid & 15;    // row-tile index: rows rt*8 .. rt*8+7
    const int ct = tid >> 4;    // col-tile index: cols ct*12 .. ct*12+11

    // prologue gather: k-tile 0 (16 values, k = kk0 + 2*i)
    float v[16];
#pragma unroll
    for (int i = 0; i < 16; ++i) {
        int k = kk0 + 2 * i;
        int p = k / 96;                  // octant
        int c = k - p * 96;              // channel
        int d = p >> 2, h = (p >> 1) & 1, wq = p & 1;
        v[i] = x[xbase + c * XS_C + d * XS_D + h * XS_H + wq];
    }

    for (int kt = 0; kt < NKT; ++kt) {
        __syncthreads();   // previous tile's FMA done; smem free

        // stage A tile + accumulate LN stats
#pragma unroll
        for (int i = 0; i < 16; ++i) {
            float val = v[i];
            A_s[kk0 + 2 * i][tl] = val;
            sum += val;
            sq  += val * val;
        }

        // stage B tile: 32x192 floats = 1536 float4, 6 per thread, gamma folded in
#pragma unroll
        for (int j = 0; j < 6; ++j) {
            int idx4 = tid + 256 * j;
            int kk   = idx4 / 48;        // 48 float4 per row
            int o4   = idx4 - kk * 48;
            int k    = kt * KT + kk;
            float4 wv = *(const float4*)(w + k * NOUT + o4 * 4);
            float gm = gs[k];
            wv.x *= gm; wv.y *= gm; wv.z *= gm; wv.w *= gm;
            *(float4*)&B_s[kk][o4 * 4] = wv;
        }
        __syncthreads();

        // prefetch next A tile into registers (LDGs overlap the FMA phase)
        if (kt + 1 < NKT) {
#pragma unroll
            for (int i = 0; i < 16; ++i) {
                int k = (kt + 1) * KT + kk0 + 2 * i;
                int p = k / 96;
                int c = k - p * 96;
                int d = p >> 2, h = (p >> 1) & 1, wq = p & 1;
                v[i] = x[xbase + c * XS_C + d * XS_D + h * XS_H + wq];
            }
        }

        // FMA over this k-tile
#pragma unroll 4
        for (int kk = 0; kk < KT; ++kk) {
            float4 a0 = *(const float4*)&A_s[kk][rt * 8];
            float4 a1 = *(const float4*)&A_s[kk][rt * 8 + 4];
            const unsigned long long* bp =
                (const unsigned long long*)&B_s[kk][ct * 12];
            unsigned long long b6[6];
#pragma unroll
            for (int j = 0; j < 6; ++j) b6[j] = bp[j];
            float ar[8] = {a0.x, a0.y, a0.z, a0.w, a1.x, a1.y, a1.z, a1.w};
#pragma unroll
            for (int r = 0; r < 8; ++r) {
                unsigned long long a2 = pack2(ar[r], ar[r]);
#pragma unroll
                for (int j = 0; j < 6; ++j) ffma2(acc[r][j], a2, b6[j]);
            }
        }
    }

    // --- LN stats reduction (2 partials per token: tid and tid+128) ---
    __syncthreads();
    float* red = &A_s[0][0];     // reuse A_s (512 floats needed)
    red[tid]       = sum;
    red[tid + 256] = sq;
    __syncthreads();
    if (tid < TM) {
        float s  = red[tid] + red[tid + 128];
        float ss = red[tid + 256] + red[tid + 384];
        float mu  = s * (1.f / 768.f);
        float var = ss * (1.f / 768.f) - mu * mu;
        mu_s[tid] = mu;
        rs_s[tid] = rsqrtf(var + 1e-5f);
    }
    __syncthreads();

    // --- epilogue: apply LN correction, store transposed ---
#pragma unroll
    for (int r = 0; r < 8; ++r) {
        int tlr = rt * 8 + r;
        float mu = mu_s[tlr];
        float rs = rs_s[tlr];
        int tt  = T0 + tlr;
        int owx = tt & 31;
        int ohy = (tt >> 5) & 31;
        int odz = (tt >> 10) & 15;
        int ob  = tt >> 14;
        int obase = ob * OS_B + odz * OS_D + ohy * OS_H + owx;
#pragma unroll
        for (int j = 0; j < 6; ++j) {
            float2 av = unpack2(acc[r][j]);
            int o0 = ct * 12 + 2 * j;
            out[obase + o0 * OS_O]       = rs * (av.x - mu * g_gv[o0])     + g_cv[o0];
            out[obase + (o0 + 1) * OS_O] = rs * (av.y - mu * g_gv[o0 + 1]) + g_cv[o0 + 1];
        }
    }
}

extern "C" void kernel_launch(void* const* d_in, const int* in_sizes, int n_in,
                              void* d_out, int out_size) {
    const float* x     = (const float*)d_in[0];
    const float* gamma = (const float*)d_in[1];
    const float* beta  = (const float*)d_in[2];
    const float* w     = (const float*)d_in[3];
    float* out = (float*)d_out;

    prep_kernel<<<1, NOUT>>>(w, gamma, beta);
    pm_kernel<<<32768 / TM, 256>>>(x, gamma, w, out);
}

// round 6
// speedup vs baseline: 1.8909x; 1.8909x over previous
#include <cuda_runtime.h>
#include <cuda_bf16.h>

// PatchMerging fused (portable tensor-core edition, sm_103 target: mma.sync/ldmatrix/cp.async):
//   octant gather -> LN stats -> bf16 hi/lo split -> HMMA GEMM (768 x 192, 3-product split)
//   -> LN-folded epilogue -> coalesced transposed store
// x:(2,96,32,64,64) f32 ; gamma,beta:(768,) ; w_red:(768,192) ; out:(2,192,16,32,32) f32
//
// acc[t,o] = sum_k y[t,k]*(gamma_k W[k,o])  via Ah*Bh + Al*Bh + Ah*Bl (bf16 splits)
// out[t,o] = rstd_t*(acc - mu_t*g[o]) + c[o],  g = sum gamma*W, c = sum beta*W

#define KTOT 768
#define NOUT 192
#define TM   128
#define KT   32
#define NKT  24

#define XS_C 131072
#define XS_D 4096
#define XS_H 64
#define XS_B 12582912
#define OS_O 16384
#define OS_B 3145728
#define OS_D 1024
#define OS_H 32

// smem layout (dynamic, byte offsets). Rows padded to 80B (conflict-free LDSM/STS).
#define AROW 80
#define AH_OFF 0
#define AL_OFF 10240                      // 128*80
#define BBASE  20480
#define BBUF   30720                      // per buffer: hi(15360) + lo(15360)
#define BH_OFF(buf) (BBASE + (buf) * BBUF)
#define BL_OFF(buf) (BBASE + (buf) * BBUF + 15360)
#define DSMEM_BYTES 81920

__device__ float g_gv[NOUT];
__device__ float g_cv[NOUT];
__device__ __align__(16) __nv_bfloat16 g_Bt_h[NOUT * KTOT];  // [n][k] gamma-scaled hi
__device__ __align__(16) __nv_bfloat16 g_Bt_l[NOUT * KTOT];  // [n][k] lo residual

// ---------------- helpers ----------------
__device__ __forceinline__ unsigned smem_u32(const void* p) {
    unsigned a;
    asm("{ .reg .u64 t; cvta.to.shared.u64 t, %1; cvt.u32.u64 %0, t; }" : "=r"(a) : "l"(p));
    return a;
}
__device__ __forceinline__ void ldsm4(unsigned& r0, unsigned& r1, unsigned& r2, unsigned& r3,
                                      unsigned addr) {
    asm volatile("ldmatrix.sync.aligned.m8n8.x4.shared.b16 {%0,%1,%2,%3}, [%4];"
                 : "=r"(r0), "=r"(r1), "=r"(r2), "=r"(r3) : "r"(addr));
}
__device__ __forceinline__ void mma_bf16(float* c, const unsigned* a, unsigned b0, unsigned b1) {
    asm volatile(
        "mma.sync.aligned.m16n8k16.row.col.f32.bf16.bf16.f32 "
        "{%0,%1,%2,%3}, {%4,%5,%6,%7}, {%8,%9}, {%0,%1,%2,%3};"
        : "+f"(c[0]), "+f"(c[1]), "+f"(c[2]), "+f"(c[3])
        : "r"(a[0]), "r"(a[1]), "r"(a[2]), "r"(a[3]), "r"(b0), "r"(b1));
}
#define CP_ASYNC16(s, g) \
    asm volatile("cp.async.cg.shared.global [%0], [%1], 16;" :: "r"(s), "l"(g))
#define CP_COMMIT() asm volatile("cp.async.commit_group;")

// ---------------- prep kernels ----------------
__global__ void prep_gc(const float* __restrict__ w, const float* __restrict__ gamma,
                        const float* __restrict__ beta) {
    int o = blockIdx.x, t = threadIdx.x;
    float g = 0.f, c = 0.f;
    for (int k = t; k < KTOT; k += 256) {
        float wv = w[k * NOUT + o];
        g += gamma[k] * wv;
        c += beta[k] * wv;
    }
    __shared__ float sg[256], sc[256];
    sg[t] = g; sc[t] = c;
    __syncthreads();
    for (int s = 128; s > 0; s >>= 1) {
        if (t < s) { sg[t] += sg[t + s]; sc[t] += sc[t + s]; }
        __syncthreads();
    }
    if (t == 0) { g_gv[o] = sg[0]; g_cv[o] = sc[0]; }
}

__global__ void prep_bt(const float* __restrict__ w, const float* __restrict__ gamma) {
    int idx = blockIdx.x * 256 + threadIdx.x;   // 192*768 = 147456
    int n = idx / KTOT;
    int k = idx - n * KTOT;
    float val = gamma[k] * w[k * NOUT + n];
    __nv_bfloat16 hi = __float2bfloat16(val);
    __nv_bfloat16 lo = __float2bfloat16(val - __bfloat162float(hi));
    g_Bt_h[n * KTOT + k] = hi;
    g_Bt_l[n * KTOT + k] = lo;
}

// ---------------- main kernel ----------------
extern __shared__ __align__(16) unsigned char dsm[];

__global__ __launch_bounds__(256, 1)
void pm_kernel(const float* __restrict__ x, float* __restrict__ out) {
    __shared__ float red[512];
    __shared__ float mu_s[TM], rs_s[TM];
    __shared__ float gv_s[NOUT], cv_s[NOUT];

    const int tid = threadIdx.x, wid = tid >> 5, lane = tid & 31;
    const unsigned dbase = smem_u32(dsm);

    if (tid < NOUT) { gv_s[tid] = g_gv[tid]; cv_s[tid] = g_cv[tid]; }

    // gather mapping: thread (tl, kk0) handles token tl, k-quarter kk0*16..+15 per tile
    const int tl  = tid & (TM - 1);
    const int kk0 = tid >> 7;
    const int t   = blockIdx.x * TM + tl;
    const int wx = t & 31, hy = (t >> 5) & 31, dz = (t >> 10) & 15, bb = t >> 14;
    const int xbase = bb * XS_B + (2 * dz) * XS_D + (2 * hy) * XS_H + 2 * wx;

    // warp GEMM tile
    const int warpM = (wid & 3) * 32;
    const int warpN = (wid >> 2) * 96;

    float acc[2][12][4];
#pragma unroll
    for (int mi = 0; mi < 2; ++mi)
#pragma unroll
        for (int nj = 0; nj < 12; ++nj)
#pragma unroll
            for (int e = 0; e < 4; ++e) acc[mi][nj][e] = 0.f;

    float sum = 0.f, sq = 0.f;

    // prologue: gather tile 0, prefetch B tile 0 into buf 0
    float v[16];
#pragma unroll
    for (int i = 0; i < 16; ++i) {
        int k = kk0 * 16 + i;
        int p = k / 96;
        int c = k - 96 * p;
        v[i] = x[xbase + c * XS_C + (p >> 2) * XS_D + ((p >> 1) & 1) * XS_H + (p & 1)];
    }
#pragma unroll
    for (int j = 0; j < 3; ++j) {
        int idx = tid + 256 * j;           // 0..767
        int n = idx >> 2, ch = idx & 3;
        long goff = (long)n * (KTOT * 2) + ch * 16;
        unsigned soff = n * AROW + ch * 16;
        CP_ASYNC16(dbase + BH_OFF(0) + soff, (const char*)g_Bt_h + goff);
        CP_ASYNC16(dbase + BL_OFF(0) + soff, (const char*)g_Bt_l + goff);
    }
    CP_COMMIT();

    for (int kt = 0; kt < NKT; ++kt) {
        const int buf = kt & 1;
        __syncthreads();   // all warps done reading A smem + B buf^1 from previous mma

        // prefetch B(kt+1) into the other buffer
        if (kt + 1 < NKT) {
#pragma unroll
            for (int j = 0; j < 3; ++j) {
                int idx = tid + 256 * j;
                int n = idx >> 2, ch = idx & 3;
                long goff = (long)n * (KTOT * 2) + (kt + 1) * (KT * 2) + ch * 16;
                unsigned soff = n * AROW + ch * 16;
                CP_ASYNC16(dbase + BH_OFF(buf ^ 1) + soff, (const char*)g_Bt_h + goff);
                CP_ASYNC16(dbase + BL_OFF(buf ^ 1) + soff, (const char*)g_Bt_l + goff);
            }
            CP_COMMIT();
        }

        // split to bf16 hi/lo, pack, store A tile; accumulate LN stats
        unsigned hw[8], lw[8];
#pragma unroll
        for (int i = 0; i < 8; ++i) {
            float a = v[2 * i], b = v[2 * i + 1];
            sum += a + b;
            sq  += a * a + b * b;
            __nv_bfloat16 ah = __float2bfloat16(a), bh = __float2bfloat16(b);
            __nv_bfloat16 al = __float2bfloat16(a - __bfloat162float(ah));
            __nv_bfloat16 bl = __float2bfloat16(b - __bfloat162float(bh));
            hw[i] = (unsigned)__bfloat16_as_ushort(ah) | ((unsigned)__bfloat16_as_ushort(bh) << 16);
            lw[i] = (unsigned)__bfloat16_as_ushort(al) | ((unsigned)__bfloat16_as_ushort(bl) << 16);
        }
        {
            unsigned rb = tl * AROW + kk0 * 32;
#pragma unroll
            for (int q = 0; q < 2; ++q) {
                *(uint4*)(dsm + AH_OFF + rb + q * 16) =
                    make_uint4(hw[4 * q], hw[4 * q + 1], hw[4 * q + 2], hw[4 * q + 3]);
                *(uint4*)(dsm + AL_OFF + rb + q * 16) =
                    make_uint4(lw[4 * q], lw[4 * q + 1], lw[4 * q + 2], lw[4 * q + 3]);
            }
        }

        if (kt < NKT - 1) { asm volatile("cp.async.wait_group 1;"); }
        else              { asm volatile("cp.async.wait_group 0;"); }
        __syncthreads();

        // ---- mma phase over this K-tile (2 k16 steps) ----
        const unsigned bh_base = dbase + BH_OFF(buf);
        const unsigned bl_base = dbase + BL_OFF(buf);
#pragma unroll
        for (int ks = 0; ks < 2; ++ks) {
            unsigned a_h[2][4], a_l[2][4];
#pragma unroll
            for (int mi = 0; mi < 2; ++mi) {
                unsigned row = warpM + mi * 16 + (lane & 15);
                unsigned ch  = ks * 2 + (lane >> 4);
                unsigned off = row * AROW + ch * 16;
                ldsm4(a_h[mi][0], a_h[mi][1], a_h[mi][2], a_h[mi][3], dbase + AH_OFF + off);
                ldsm4(a_l[mi][0], a_l[mi][1], a_l[mi][2], a_l[mi][3], dbase + AL_OFF + off);
            }
#pragma unroll
            for (int njp = 0; njp < 6; ++njp) {
                unsigned brow = warpN + njp * 16 + ((lane >> 4) << 3) + (lane & 7);
                unsigned bch  = ks * 2 + ((lane >> 3) & 1);
                unsigned boff = brow * AROW + bch * 16;
                unsigned bh0, bh1, bh2, bh3, bl0, bl1, bl2, bl3;
                ldsm4(bh0, bh1, bh2, bh3, bh_base + boff);
                ldsm4(bl0, bl1, bl2, bl3, bl_base + boff);
#pragma unroll
                for (int mi = 0; mi < 2; ++mi) {
                    float* c0 = acc[mi][njp * 2];
                    float* c1 = acc[mi][njp * 2 + 1];
                    mma_bf16(c0, a_h[mi], bh0, bh1);
                    mma_bf16(c1, a_h[mi], bh2, bh3);
                    mma_bf16(c0, a_l[mi], bh0, bh1);
                    mma_bf16(c1, a_l[mi], bh2, bh3);
                    mma_bf16(c0, a_h[mi], bl0, bl1);
                    mma_bf16(c1, a_h[mi], bl2, bl3);
                }
            }
        }

        // gather next A tile (overlaps with mma scheduling)
        if (kt + 1 < NKT) {
#pragma unroll
            for (int i = 0; i < 16; ++i) {
                int k = (kt + 1) * KT + kk0 * 16 + i;
                int p = k / 96;
                int c = k - 96 * p;
                v[i] = x[xbase + c * XS_C + (p >> 2) * XS_D + ((p >> 1) & 1) * XS_H + (p & 1)];
            }
        }
    }

    // ---- LN stats reduction ----
    red[tid] = sum;
    red[tid + 256] = sq;
    __syncthreads();
    if (tid < TM) {
        float s  = red[tid] + red[tid + TM];
        float ss = red[tid + 256] + red[tid + 256 + TM];
        float mu  = s * (1.f / 768.f);
        float var = ss * (1.f / 768.f) - mu * mu;
        mu_s[tid] = mu;
        rs_s[tid] = rsqrtf(var + 1e-5f);
    }
    __syncthreads();

    // ---- epilogue: LN fold + transpose through smem, coalesced stores ----
    float* etile = (float*)dsm;   // [96][132] f32 = 50688 B (reuses staging smem)
    const int T0 = blockIdx.x * TM;
    const int base0 = (T0 >> 14) * OS_B + ((T0 >> 10) & 15) * OS_D + ((T0 >> 5) & 31) * OS_H;
    const int lane4 = lane >> 2, lpair = (lane & 3) * 2;

#pragma unroll
    for (int h = 0; h < 2; ++h) {
        if ((wid >> 2) == h) {
#pragma unroll
            for (int mi = 0; mi < 2; ++mi)
#pragma unroll
                for (int nj = 0; nj < 12; ++nj) {
                    int nloc = nj * 8 + lpair;
                    int o = h * 96 + nloc;
                    float g0 = gv_s[o], g1 = gv_s[o + 1];
                    float c0 = cv_s[o], c1 = cv_s[o + 1];
#pragma unroll
                    for (int e = 0; e < 2; ++e) {
                        int row = warpM + mi * 16 + lane4 + e * 8;
                        float mu = mu_s[row], rs = rs_s[row];
                        etile[nloc * 132 + row]       = rs * (acc[mi][nj][2 * e]     - mu * g0) + c0;
                        etile[(nloc + 1) * 132 + row] = rs * (acc[mi][nj][2 * e + 1] - mu * g1) + c1;
                    }
                }
        }
        __syncthreads();
#pragma unroll
        for (int j = 0; j < 48; ++j) {
            int idx = tid + 256 * j;
            int ol = idx >> 7, pos = idx & 127;
            out[base0 + (h * 96 + ol) * OS_O + pos] = etile[ol * 132 + pos];
        }
        __syncthreads();
    }
}

extern "C" void kernel_launch(void* const* d_in, const int* in_sizes, int n_in,
                              void* d_out, int out_size) {
    const float* x     = (const float*)d_in[0];
    const float* gamma = (const float*)d_in[1];
    const float* beta  = (const float*)d_in[2];
    const float* w     = (const float*)d_in[3];
    float* out = (float*)d_out;

    cudaFuncSetAttribute(pm_kernel, cudaFuncAttributeMaxDynamicSharedMemorySize, DSMEM_BYTES);

    prep_gc<<<NOUT, 256>>>(w, gamma, beta);
    prep_bt<<<(NOUT * KTOT) / 256, 256>>>(w, gamma);
    pm_kernel<<<32768 / TM, 256, DSMEM_BYTES>>>(x, out);
}

// round 8
// speedup vs baseline: 2.2427x; 1.1860x over previous
#include <cuda_runtime.h>
#include <cuda_fp16.h>

// PatchMerging fused (portable HMMA edition, fp16 2-product split):
//   octant gather -> LN stats -> fp16 hi/lo split (A) -> HMMA GEMM (768 x 192)
//   -> LN-folded epilogue -> coalesced transposed store
// x:(2,96,32,64,64) f32 ; gamma,beta:(768,) ; w_red:(768,192) ; out:(2,192,16,32,32) f32
//
// acc[t,o] = sum_k y[t,k]*(gamma_k W[k,o])  via Ah*Bh + Al*Bh  (A fp16-split exact to 2^-22,
//   B single fp16 -> rel err ~2^-12)
// out[t,o] = rstd_t*(acc - mu_t*g[o]) + c[o],  g = sum gamma*W, c = sum beta*W

#define KTOT 768
#define NOUT 192
#define TM   128
#define KT   32
#define NKT  24

#define XS_C 131072
#define XS_D 4096
#define XS_H 64
#define XS_B 12582912
#define OS_O 16384
#define OS_B 3145728
#define OS_D 1024
#define OS_H 32

// smem layout (dynamic, byte offsets). Rows padded to 80B (conflict-free LDSM/STS).
#define AROW 80
#define AH_OFF 0
#define AL_OFF 10240                      // 128*80
#define BBASE  20480
#define BBUF   15360                      // per buffer: hi only (192*80)
#define BH_OFF(buf) (BBASE + (buf) * BBUF)
#define DSMEM_BYTES 53248                 // >= 51200, also covers epilogue tile (50688)

#define PREP_KROWS 32
#define PREP_BLKS  24                     // 768/32

__device__ float g_gv[NOUT];
__device__ float g_cv[NOUT];
__device__ float g_part_g[PREP_BLKS * NOUT];
__device__ float g_part_c[PREP_BLKS * NOUT];
__device__ __align__(16) __half g_Bt_h[NOUT * KTOT];  // [n][k] gamma-scaled fp16

// ---------------- helpers ----------------
__device__ __forceinline__ unsigned smem_u32(const void* p) {
    unsigned a;
    asm("{ .reg .u64 t; cvta.to.shared.u64 t, %1; cvt.u32.u64 %0, t; }" : "=r"(a) : "l"(p));
    return a;
}
__device__ __forceinline__ void ldsm4(unsigned& r0, unsigned& r1, unsigned& r2, unsigned& r3,
                                      unsigned addr) {
    asm volatile("ldmatrix.sync.aligned.m8n8.x4.shared.b16 {%0,%1,%2,%3}, [%4];"
                 : "=r"(r0), "=r"(r1), "=r"(r2), "=r"(r3) : "r"(addr));
}
__device__ __forceinline__ void mma_f16(float* c, const unsigned* a, unsigned b0, unsigned b1) {
    asm volatile(
        "mma.sync.aligned.m16n8k16.row.col.f32.f16.f16.f32 "
        "{%0,%1,%2,%3}, {%4,%5,%6,%7}, {%8,%9}, {%0,%1,%2,%3};"
        : "+f"(c[0]), "+f"(c[1]), "+f"(c[2]), "+f"(c[3])
        : "r"(a[0]), "r"(a[1]), "r"(a[2]), "r"(a[3]), "r"(b0), "r"(b1));
}
#define CP_ASYNC16(s, g) \
    asm volatile("cp.async.cg.shared.global [%0], [%1], 16;" :: "r"(s), "l"(g))
#define CP_COMMIT() asm volatile("cp.async.commit_group;")

// ---------------- prep kernels ----------------
// prep1: coalesced tile load of w, produce gamma-scaled fp16 B^T and per-block g/c partials
__global__ __launch_bounds__(256)
void prep1(const float* __restrict__ w, const float* __restrict__ gamma,
           const float* __restrict__ beta) {
    __shared__ float ts[PREP_KROWS][NOUT + 1];   // stride 193: conflict-free column reads
    __shared__ float gam_s[PREP_KROWS], bet_s[PREP_KROWS];
    const int tid = threadIdx.x;
    const int k0  = blockIdx.x * PREP_KROWS;

    if (tid < PREP_KROWS) {
        gam_s[tid] = gamma[k0 + tid];
        bet_s[tid] = beta[k0 + tid];
    }
    for (int i = tid; i < PREP_KROWS * NOUT; i += 256) {
        int r = i / NOUT, n = i - r * NOUT;
        ts[r][n] = w[(k0 + r) * NOUT + n];
    }
    __syncthreads();

    // g/c partials for this k-slab
    if (tid < NOUT) {
        float g = 0.f, c = 0.f;
#pragma unroll
        for (int r = 0; r < PREP_KROWS; ++r) {
            float wv = ts[r][tid];
            g += gam_s[r] * wv;
            c += bet_s[r] * wv;
        }
        g_part_g[blockIdx.x * NOUT + tid] = g;
        g_part_c[blockIdx.x * NOUT + tid] = c;
    }

    // B^T fp16: 192 n-rows x 32 k = 768 uint4 (8 halves each)
#pragma unroll
    for (int j = 0; j < 3; ++j) {
        int e = tid + 256 * j;
        int n = e >> 2, ch = e & 3;
        __half hbuf[8];
#pragma unroll
        for (int u = 0; u < 8; ++u) {
            int kl = ch * 8 + u;
            hbuf[u] = __float2half_rn(gam_s[kl] * ts[kl][n]);
        }
        *(uint4*)((char*)g_Bt_h + (long)n * (KTOT * 2) + k0 * 2 + ch * 16) = *(uint4*)hbuf;
    }
}

__global__ void prep2() {
    int o = threadIdx.x;   // 192 threads
    float g = 0.f, c = 0.f;
#pragma unroll
    for (int b = 0; b < PREP_BLKS; ++b) {
        g += g_part_g[b * NOUT + o];
        c += g_part_c[b * NOUT + o];
    }
    g_gv[o] = g;
    g_cv[o] = c;
}

// ---------------- main kernel ----------------
extern __shared__ __align__(16) unsigned char dsm[];

__global__ __launch_bounds__(256, 1)
void pm_kernel(const float* __restrict__ x, float* __restrict__ out) {
    __shared__ float red[512];
    __shared__ float mu_s[TM], rs_s[TM];
    __shared__ float gv_s[NOUT], cv_s[NOUT];

    const int tid = threadIdx.x, wid = tid >> 5, lane = tid & 31;
    const unsigned dbase = smem_u32(dsm);

    if (tid < NOUT) { gv_s[tid] = g_gv[tid]; cv_s[tid] = g_cv[tid]; }

    // gather mapping: thread (tl, kk0) handles token tl, k-quarter kk0*16..+15 per tile
    const int tl  = tid & (TM - 1);
    const int kk0 = tid >> 7;
    const int t   = blockIdx.x * TM + tl;
    const int wx = t & 31, hy = (t >> 5) & 31, dz = (t >> 10) & 15, bb = t >> 14;
    const int xbase = bb * XS_B + (2 * dz) * XS_D + (2 * hy) * XS_H + 2 * wx;

    // warp GEMM tile
    const int warpM = (wid & 3) * 32;
    const int warpN = (wid >> 2) * 96;

    float acc[2][12][4];
#pragma unroll
    for (int mi = 0; mi < 2; ++mi)
#pragma unroll
        for (int nj = 0; nj < 12; ++nj)
#pragma unroll
            for (int e = 0; e < 4; ++e) acc[mi][nj][e] = 0.f;

    float sum = 0.f, sq = 0.f;

    // prologue: gather tile 0, prefetch B tile 0 into buf 0
    float v[16];
#pragma unroll
    for (int i = 0; i < 16; ++i) {
        int k = kk0 * 16 + i;
        int p = k / 96;
        int c = k - 96 * p;
        v[i] = x[xbase + c * XS_C + (p >> 2) * XS_D + ((p >> 1) & 1) * XS_H + (p & 1)];
    }
#pragma unroll
    for (int j = 0; j < 3; ++j) {
        int idx = tid + 256 * j;           // 0..767
        int n = idx >> 2, ch = idx & 3;
        long goff = (long)n * (KTOT * 2) + ch * 16;
        unsigned soff = n * AROW + ch * 16;
        CP_ASYNC16(dbase + BH_OFF(0) + soff, (const char*)g_Bt_h + goff);
    }
    CP_COMMIT();

    for (int kt = 0; kt < NKT; ++kt) {
        const int buf = kt & 1;
        __syncthreads();   // all warps done reading A smem + B buf^1 from previous mma

        // prefetch B(kt+1) into the other buffer
        if (kt + 1 < NKT) {
#pragma unroll
            for (int j = 0; j < 3; ++j) {
                int idx = tid + 256 * j;
                int n = idx >> 2, ch = idx & 3;
                long goff = (long)n * (KTOT * 2) + (kt + 1) * (KT * 2) + ch * 16;
                unsigned soff = n * AROW + ch * 16;
                CP_ASYNC16(dbase + BH_OFF(buf ^ 1) + soff, (const char*)g_Bt_h + goff);
            }
            CP_COMMIT();
        }

        // split to fp16 hi/lo, pack, store A tile; accumulate LN stats
        unsigned hw[8], lw[8];
#pragma unroll
        for (int i = 0; i < 8; ++i) {
            float a = v[2 * i], b = v[2 * i + 1];
            sum += a + b;
            sq  += a * a + b * b;
            __half ah = __float2half_rn(a), bh = __float2half_rn(b);
            __half al = __float2half_rn(a - __half2float(ah));
            __half bl = __float2half_rn(b - __half2float(bh));
            hw[i] = (unsigned)__half_as_ushort(ah) | ((unsigned)__half_as_ushort(bh) << 16);
            lw[i] = (unsigned)__half_as_ushort(al) | ((unsigned)__half_as_ushort(bl) << 16);
        }
        {
            unsigned rb = tl * AROW + kk0 * 32;
#pragma unroll
            for (int q = 0; q < 2; ++q) {
                *(uint4*)(dsm + AH_OFF + rb + q * 16) =
                    make_uint4(hw[4 * q], hw[4 * q + 1], hw[4 * q + 2], hw[4 * q + 3]);
                *(uint4*)(dsm + AL_OFF + rb + q * 16) =
                    make_uint4(lw[4 * q], lw[4 * q + 1], lw[4 * q + 2], lw[4 * q + 3]);
            }
        }

        if (kt < NKT - 1) { asm volatile("cp.async.wait_group 1;"); }
        else              { asm volatile("cp.async.wait_group 0;"); }
        __syncthreads();

        // ---- mma phase over this K-tile (2 k16 steps, 2 products) ----
        const unsigned bh_base = dbase + BH_OFF(buf);
#pragma unroll
        for (int ks = 0; ks < 2; ++ks) {
            unsigned a_h[2][4], a_l[2][4];
#pragma unroll
            for (int mi = 0; mi < 2; ++mi) {
                unsigned row = warpM + mi * 16 + (lane & 15);
                unsigned ch  = ks * 2 + (lane >> 4);
                unsigned off = row * AROW + ch * 16;
                ldsm4(a_h[mi][0], a_h[mi][1], a_h[mi][2], a_h[mi][3], dbase + AH_OFF + off);
                ldsm4(a_l[mi][0], a_l[mi][1], a_l[mi][2], a_l[mi][3], dbase + AL_OFF + off);
            }
#pragma unroll
            for (int njp = 0; njp < 6; ++njp) {
                unsigned brow = warpN + njp * 16 + ((lane >> 4) << 3) + (lane & 7);
                unsigned bch  = ks * 2 + ((lane >> 3) & 1);
                unsigned boff = brow * AROW + bch * 16;
                unsigned bh0, bh1, bh2, bh3;
                ldsm4(bh0, bh1, bh2, bh3, bh_base + boff);
#pragma unroll
                for (int mi = 0; mi < 2; ++mi) {
                    float* c0 = acc[mi][njp * 2];
                    float* c1 = acc[mi][njp * 2 + 1];
                    mma_f16(c0, a_h[mi], bh0, bh1);
                    mma_f16(c1, a_h[mi], bh2, bh3);
                    mma_f16(c0, a_l[mi], bh0, bh1);
                    mma_f16(c1, a_l[mi], bh2, bh3);
                }
            }
        }

        // gather next A tile (overlaps with mma scheduling)
        if (kt + 1 < NKT) {
#pragma unroll
            for (int i = 0; i < 16; ++i) {
                int k = (kt + 1) * KT + kk0 * 16 + i;
                int p = k / 96;
                int c = k - 96 * p;
                v[i] = x[xbase + c * XS_C + (p >> 2) * XS_D + ((p >> 1) & 1) * XS_H + (p & 1)];
            }
        }
    }

    // ---- LN stats reduction ----
    red[tid] = sum;
    red[tid + 256] = sq;
    __syncthreads();
    if (tid < TM) {
        float s  = red[tid] + red[tid + TM];
        float ss = red[tid + 256] + red[tid + 256 + TM];
        float mu  = s * (1.f / 768.f);
        float var = ss * (1.f / 768.f) - mu * mu;
        mu_s[tid] = mu;
        rs_s[tid] = rsqrtf(var + 1e-5f);
    }
    __syncthreads();

    // ---- epilogue: LN fold + transpose through smem, coalesced stores ----
    float* etile = (float*)dsm;   // [96][132] f32 = 50688 B (reuses staging smem)
    const int T0 = blockIdx.x * TM;
    const int base0 = (T0 >> 14) * OS_B + ((T0 >> 10) & 15) * OS_D + ((T0 >> 5) & 31) * OS_H;
    const int lane4 = lane >> 2, lpair = (lane & 3) * 2;

#pragma unroll
    for (int h = 0; h < 2; ++h) {
        if ((wid >> 2) == h) {
#pragma unroll
            for (int mi = 0; mi < 2; ++mi)
#pragma unroll
                for (int nj = 0; nj < 12; ++nj) {
                    int nloc = nj * 8 + lpair;
                    int o = h * 96 + nloc;
                    float g0 = gv_s[o], g1 = gv_s[o + 1];
                    float c0 = cv_s[o], c1 = cv_s[o + 1];
#pragma unroll
                    for (int e = 0; e < 2; ++e) {
                        int row = warpM + mi * 16 + lane4 + e * 8;
                        float mu = mu_s[row], rs = rs_s[row];
                        etile[nloc * 132 + row]       = rs * (acc[mi][nj][2 * e]     - mu * g0) + c0;
                        etile[(nloc + 1) * 132 + row] = rs * (acc[mi][nj][2 * e + 1] - mu * g1) + c1;
                    }
                }
        }
        __syncthreads();
#pragma unroll
        for (int j = 0; j < 48; ++j) {
            int idx = tid + 256 * j;
            int ol = idx >> 7, pos = idx & 127;
            out[base0 + (h * 96 + ol) * OS_O + pos] = etile[ol * 132 + pos];
        }
        __syncthreads();
    }
}

extern "C" void kernel_launch(void* const* d_in, const int* in_sizes, int n_in,
                              void* d_out, int out_size) {
    const float* x     = (const float*)d_in[0];
    const float* gamma = (const float*)d_in[1];
    const float* beta  = (const float*)d_in[2];
    const float* w     = (const float*)d_in[3];
    float* out = (float*)d_out;

    cudaFuncSetAttribute(pm_kernel, cudaFuncAttributeMaxDynamicSharedMemorySize, DSMEM_BYTES);

    prep1<<<PREP_BLKS, 256>>>(w, gamma, beta);
    prep2<<<1, NOUT>>>();
    pm_kernel<<<32768 / TM, 256, DSMEM_BYTES>>>(x, out);
}

// round 10
// speedup vs baseline: 3.4270x; 1.5281x over previous
#include <cuda_runtime.h>
#include <cuda_fp16.h>

// PatchMerging fused (HMMA, fp16 2-product split, occ-2 edition):
//   paired-octant float2 gather (K-tile permutation) -> LN stats -> fp16 hi/lo split (A)
//   -> mma.sync GEMM (768 x 192) -> LN-folded epilogue -> coalesced transposed store
// x:(2,96,32,64,64) f32 ; gamma,beta:(768,) ; w_red:(768,192) ; out:(2,192,16,32,32) f32
//
// acc[t,o] = sum_k y[t,k]*(gamma_k W[k,o])  via Ah*Bh + Al*Bh
// out[t,o] = rstd_t*(acc - mu_t*g[o]) + c[o]
//
// K-tile trick: k = p*96 + c, tiles of 32 k have constant octant p (96 = 3*32).
// Octants p (even) and p+1 differ only by +1 in w -> one float2 load serves
// tiles kt and kt+3. Process order per group of 6: 0,3,1,4,2,5.

#define KTOT 768
#define NOUT 192
#define TM   64
#define KT   32

#define XS_C 131072
#define XS_D 4096
#define XS_H 64
#define XS_B 12582912
#define OS_O 16384
#define OS_B 3145728
#define OS_D 1024
#define OS_H 32

// smem (dynamic): A 64x80 x2 (hi/lo), B 192x80 double-buffered
#define AROW 80
#define AH_OFF 0
#define AL_OFF 5120
#define BBASE  10240
#define BBUF   15360
#define BH_OFF(buf) (BBASE + (buf) * BBUF)
#define DSMEM_BYTES 40960            // also covers epilogue tile 96*68*4 = 26112

#define PREP_KROWS 8
#define PREP_BLKS  96

__device__ float g_gv[NOUT];
__device__ float g_cv[NOUT];
__device__ float g_part_g[PREP_BLKS * NOUT];
__device__ float g_part_c[PREP_BLKS * NOUT];
__device__ __align__(16) __half g_Bt_h[NOUT * KTOT];   // [n][k] gamma-scaled fp16

// ---------------- helpers ----------------
__device__ __forceinline__ unsigned smem_u32(const void* p) {
    unsigned a;
    asm("{ .reg .u64 t; cvta.to.shared.u64 t, %1; cvt.u32.u64 %0, t; }" : "=r"(a) : "l"(p));
    return a;
}
__device__ __forceinline__ void ldsm4(unsigned& r0, unsigned& r1, unsigned& r2, unsigned& r3,
                                      unsigned addr) {
    asm volatile("ldmatrix.sync.aligned.m8n8.x4.shared.b16 {%0,%1,%2,%3}, [%4];"
                 : "=r"(r0), "=r"(r1), "=r"(r2), "=r"(r3) : "r"(addr));
}
__device__ __forceinline__ void mma_f16(float* c, const unsigned* a, unsigned b0, unsigned b1) {
    asm volatile(
        "mma.sync.aligned.m16n8k16.row.col.f32.f16.f16.f32 "
        "{%0,%1,%2,%3}, {%4,%5,%6,%7}, {%8,%9}, {%0,%1,%2,%3};"
        : "+f"(c[0]), "+f"(c[1]), "+f"(c[2]), "+f"(c[3])
        : "r"(a[0]), "r"(a[1]), "r"(a[2]), "r"(a[3]), "r"(b0), "r"(b1));
}
#define CP_ASYNC16(s, g) \
    asm volatile("cp.async.cg.shared.global [%0], [%1], 16;" :: "r"(s), "l"(g))
#define CP_COMMIT() asm volatile("cp.async.commit_group;")

// ---------------- prep kernels ----------------
__global__ __launch_bounds__(256)
void prep1(const float* __restrict__ w, const float* __restrict__ gamma,
           const float* __restrict__ beta) {
    __shared__ float ts[PREP_KROWS][NOUT + 1];
    __shared__ float gam_s[PREP_KROWS], bet_s[PREP_KROWS];
    const int tid = threadIdx.x;
    const int k0  = blockIdx.x * PREP_KROWS;

    if (tid < PREP_KROWS) {
        gam_s[tid] = gamma[k0 + tid];
        bet_s[tid] = beta[k0 + tid];
    }
    for (int i = tid; i < PREP_KROWS * NOUT; i += 256) {
        int r = i / NOUT, n = i - r * NOUT;
        ts[r][n] = w[(k0 + r) * NOUT + n];
    }
    __syncthreads();

    if (tid < NOUT) {
        float g = 0.f, c = 0.f;
        __half hbuf[PREP_KROWS];
#pragma unroll
        for (int r = 0; r < PREP_KROWS; ++r) {
            float wv = ts[r][tid];
            g += gam_s[r] * wv;
            c += bet_s[r] * wv;
            hbuf[r] = __float2half_rn(gam_s[r] * wv);
        }
        g_part_g[blockIdx.x * NOUT + tid] = g;
        g_part_c[blockIdx.x * NOUT + tid] = c;
        *(uint4*)(&g_Bt_h[tid * KTOT + k0]) = *(uint4*)hbuf;
    }
}

__global__ void prep2() {
    int o = threadIdx.x;   // 192 threads
    float g = 0.f, c = 0.f;
#pragma unroll 8
    for (int b = 0; b < PREP_BLKS; ++b) {
        g += g_part_g[b * NOUT + o];
        c += g_part_c[b * NOUT + o];
    }
    g_gv[o] = g;
    g_cv[o] = c;
}

// ---------------- main kernel ----------------
extern __shared__ __align__(16) unsigned char dsm[];

__global__ __launch_bounds__(256, 2)
void pm_kernel(const float* __restrict__ x, float* __restrict__ out) {
    __shared__ float red[512];
    __shared__ float mu_s[TM], rs_s[TM];
    __shared__ float gv_s[NOUT], cv_s[NOUT];

    const int tid = threadIdx.x, wid = tid >> 5, lane = tid & 31;
    const unsigned dbase = smem_u32(dsm);

    if (tid < NOUT) { gv_s[tid] = g_gv[tid]; cv_s[tid] = g_cv[tid]; }

    // gather mapping: thread (tl, kk0): token tl, 8 k's per tile (kk0*8..+7)
    const int tl  = tid & (TM - 1);
    const int kk0 = tid >> 6;
    const int t   = blockIdx.x * TM + tl;
    const int wx = t & 31, hy = (t >> 5) & 31, dz = (t >> 10) & 15, bb = t >> 14;
    const float* xb = x + bb * XS_B + (2 * dz) * XS_D + (2 * hy) * XS_H + 2 * wx;

    // warp GEMM tile: m32 x n48
    const int warpM = (wid & 1) * 32;
    const int warpN = (wid >> 1) * 48;

    float acc[2][6][4];
#pragma unroll
    for (int mi = 0; mi < 2; ++mi)
#pragma unroll
        for (int nj = 0; nj < 6; ++nj)
#pragma unroll
            for (int e = 0; e < 4; ++e) acc[mi][nj][e] = 0.f;

    float sum = 0.f, sq = 0.f;
    float v[8], stash[8];

    // prologue: gather tile kt=0 (octant p=0, c0=0) via float2; stash partner (p=1 -> tile 3)
#pragma unroll
    for (int i = 0; i < 8; ++i) {
        float2 xv = *(const float2*)(xb + (kk0 * 8 + i) * XS_C);
        v[i] = xv.x;
        stash[i] = xv.y;
    }
    // prefetch B tile 0 -> buf 0
#pragma unroll
    for (int j = 0; j < 3; ++j) {
        int idx = tid + 256 * j;
        int n = idx >> 2, ch = idx & 3;
        CP_ASYNC16(dbase + BH_OFF(0) + n * AROW + ch * 16,
                   (const char*)g_Bt_h + (long)n * (KTOT * 2) + ch * 16);
    }
    CP_COMMIT();

    // processed K-tile order per group of 6: 0,3,1,4,2,5 (+6g)
    for (int g = 0; g < 4; ++g) {
#pragma unroll
        for (int r = 0; r < 6; ++r) {
            const int buf = r & 1;
            const bool last = (g == 3) && (r == 5);
            // kperm[pos+1] - 6g:
            const int ktn_rel = (r < 5) ? ((r & 1) ? ((r + 1) >> 1) : ((r + 1) >> 1) + 3) : 6;
            __syncthreads();   // A smem + B[buf^1] free

            // prefetch next B tile
            if (!last) {
                const int ktn = g * 6 + ktn_rel;
#pragma unroll
                for (int j = 0; j < 3; ++j) {
                    int idx = tid + 256 * j;
                    int n = idx >> 2, ch = idx & 3;
                    CP_ASYNC16(dbase + BH_OFF(buf ^ 1) + n * AROW + ch * 16,
                               (const char*)g_Bt_h + (long)n * (KTOT * 2) + ktn * (KT * 2) + ch * 16);
                }
                CP_COMMIT();
            }

            // split v -> fp16 hi/lo, store A tile, LN stats
            {
                unsigned hw[4], lw[4];
#pragma unroll
                for (int i = 0; i < 4; ++i) {
                    float a = v[2 * i], b = v[2 * i + 1];
                    sum += a + b;
                    sq  += a * a + b * b;
                    __half ah = __float2half_rn(a), bh = __float2half_rn(b);
                    __half al = __float2half_rn(a - __half2float(ah));
                    __half bl = __float2half_rn(b - __half2float(bh));
                    hw[i] = (unsigned)__half_as_ushort(ah) | ((unsigned)__half_as_ushort(bh) << 16);
                    lw[i] = (unsigned)__half_as_ushort(al) | ((unsigned)__half_as_ushort(bl) << 16);
                }
                unsigned rb = tl * AROW + kk0 * 16;
                *(uint4*)(dsm + AH_OFF + rb) = make_uint4(hw[0], hw[1], hw[2], hw[3]);
                *(uint4*)(dsm + AL_OFF + rb) = make_uint4(lw[0], lw[1], lw[2], lw[3]);
            }

            if (!last) { asm volatile("cp.async.wait_group 1;"); }
            else       { asm volatile("cp.async.wait_group 0;"); }
            __syncthreads();

            // ---- mma over this K-tile ----
            const unsigned bh_base = dbase + BH_OFF(buf);
#pragma unroll
            for (int ks = 0; ks < 2; ++ks) {
                unsigned a_h[2][4], a_l[2][4];
#pragma unroll
                for (int mi = 0; mi < 2; ++mi) {
                    unsigned row = warpM + mi * 16 + (lane & 15);
                    unsigned off = row * AROW + (ks * 2 + (lane >> 4)) * 16;
                    ldsm4(a_h[mi][0], a_h[mi][1], a_h[mi][2], a_h[mi][3], dbase + AH_OFF + off);
                    ldsm4(a_l[mi][0], a_l[mi][1], a_l[mi][2], a_l[mi][3], dbase + AL_OFF + off);
                }
#pragma unroll
                for (int j = 0; j < 3; ++j) {
                    unsigned brow = warpN + j * 16 + ((lane >> 4) << 3) + (lane & 7);
                    unsigned boff = brow * AROW + (ks * 2 + ((lane >> 3) & 1)) * 16;
                    unsigned b0, b1, b2, b3;
                    ldsm4(b0, b1, b2, b3, bh_base + boff);
#pragma unroll
                    for (int mi = 0; mi < 2; ++mi) {
                        float* c0 = acc[mi][j * 2];
                        float* c1 = acc[mi][j * 2 + 1];
                        mma_f16(c0, a_h[mi], b0, b1);
                        mma_f16(c1, a_h[mi], b2, b3);
                        mma_f16(c0, a_l[mi], b0, b1);
                        mma_f16(c1, a_l[mi], b2, b3);
                    }
                }
            }

            // prepare v for next tile
            if (!last) {
                if ((r & 1) == 0) {
                    // next tile is the stashed odd-octant partner
#pragma unroll
                    for (int i = 0; i < 8; ++i) v[i] = stash[i];
                } else {
                    // next tile is even-octant: float2 load, stash partner
                    const int ktn = g * 6 + ktn_rel;     // r=1->6g+1, r=3->6g+2, r=5->6g+6
                    const int p  = (r == 5) ? 2 * g + 2 : 2 * g;
                    const int c0 = (r == 1) ? 32 : (r == 3) ? 64 : 0;
                    const int offs = (p >> 2) * XS_D + ((p >> 1) & 1) * XS_H;
                    (void)ktn;
#pragma unroll
                    for (int i = 0; i < 8; ++i) {
                        float2 xv = *(const float2*)(xb + (c0 + kk0 * 8 + i) * XS_C + offs);
                        v[i] = xv.x;
                        stash[i] = xv.y;
                    }
                }
            }
        }
    }

    // ---- LN stats reduction (4 partials per token) ----
    red[tid] = sum;
    red[tid + 256] = sq;
    __syncthreads();
    if (tid < TM) {
        float s  = red[tid] + red[tid + 64] + red[tid + 128] + red[tid + 192];
        float ss = red[tid + 256] + red[tid + 320] + red[tid + 384] + red[tid + 448];
        float mu  = s * (1.f / 768.f);
        float var = ss * (1.f / 768.f) - mu * mu;
        mu_s[tid] = mu;
        rs_s[tid] = rsqrtf(var + 1e-5f);
    }
    __syncthreads();

    // ---- epilogue: LN fold + transpose via smem, coalesced stores ----
    float* etile = (float*)dsm;   // [96][68] f32 = 26112 B
    const int T0 = blockIdx.x * TM;
    const int base0 = (T0 >> 14) * OS_B + ((T0 >> 10) & 15) * OS_D + ((T0 >> 5) & 31) * OS_H;
    const int lane4 = lane >> 2, lpair = (lane & 3) * 2;

#pragma unroll
    for (int ph = 0; ph < 2; ++ph) {
        if ((warpN / 96) == ph) {
            const int nb = warpN - ph * 96;
#pragma unroll
            for (int mi = 0; mi < 2; ++mi)
#pragma unroll
                for (int nj = 0; nj < 6; ++nj) {
                    int nloc = nb + nj * 8 + lpair;
                    int o = ph * 96 + nloc;
                    float g0 = gv_s[o], g1 = gv_s[o + 1];
                    float c0 = cv_s[o], c1 = cv_s[o + 1];
#pragma unroll
                    for (int e = 0; e < 2; ++e) {
                        int row = warpM + mi * 16 + lane4 + e * 8;
                        float mu = mu_s[row], rs = rs_s[row];
                        etile[nloc * 68 + row]       = rs * (acc[mi][nj][2 * e]     - mu * g0) + c0;
                        etile[(nloc + 1) * 68 + row] = rs * (acc[mi][nj][2 * e + 1] - mu * g1) + c1;
                    }
                }
        }
        __syncthreads();
#pragma unroll
        for (int j = 0; j < 24; ++j) {
            int idx = tid + 256 * j;
            int ol = idx >> 6, pos = idx & 63;
            out[base0 + (ph * 96 + ol) * OS_O + pos] = etile[ol * 68 + pos];
        }
        __syncthreads();
    }
}

extern "C" void kernel_launch(void* const* d_in, const int* in_sizes, int n_in,
                              void* d_out, int out_size) {
    const float* x     = (const float*)d_in[0];
    const float* gamma = (const float*)d_in[1];
    const float* beta  = (const float*)d_in[2];
    const float* w     = (const float*)d_in[3];
    float* out = (float*)d_out;

    cudaFuncSetAttribute(pm_kernel, cudaFuncAttributeMaxDynamicSharedMemorySize, DSMEM_BYTES);

    prep1<<<PREP_BLKS, 256>>>(w, gamma, beta);
    prep2<<<1, NOUT>>>();
    pm_kernel<<<32768 / TM, 256, DSMEM_BYTES>>>(x, out);
}

// round 11
// speedup vs baseline: 4.2206x; 1.2316x over previous
#include <cuda_runtime.h>
#include <cuda_fp16.h>

// PatchMerging fused (HMMA, single fp16 product, occ-2):
//   paired-octant float2 gather (K-tile permutation) -> LN stats -> fp16 A
//   -> mma.sync GEMM (768 x 192) -> LN-folded epilogue -> coalesced transposed store
// x:(2,96,32,64,64) f32 ; gamma,beta:(768,) ; w_red:(768,192) ; out:(2,192,16,32,32) f32
//
// acc[t,o] = sum_k y[t,k]*(gamma_k W[k,o])  with A,B both fp16 (indep quant walks ~2^-12)
// out[t,o] = rstd_t*(acc - mu_t*g[o]) + c[o]
//
// K-tile trick: k = p*96 + c, tiles of 32 k have constant octant p (96 = 3*32).
// Octants p (even) and p+1 differ only by +1 in w -> one float2 load serves
// tiles kt and kt+3. Process order per group of 6: 0,3,1,4,2,5.

#define KTOT 768
#define NOUT 192
#define TM   64
#define KT   32

#define XS_C 131072
#define XS_D 4096
#define XS_H 64
#define XS_B 12582912
#define OS_O 16384
#define OS_B 3145728
#define OS_D 1024
#define OS_H 32

// smem (dynamic): A 64x80 (hi only), B 192x80 double-buffered
#define AROW 80
#define AH_OFF 0
#define BBASE  5120
#define BBUF   15360
#define BH_OFF(buf) (BBASE + (buf) * BBUF)
#define DSMEM_BYTES 35840            // also covers epilogue tile 96*68*4 = 26112

#define PREP_KROWS 8
#define PREP_BLKS  96

__device__ float g_gv[NOUT];
__device__ float g_cv[NOUT];
__device__ float g_part_g[PREP_BLKS * NOUT];
__device__ float g_part_c[PREP_BLKS * NOUT];
__device__ __align__(16) __half g_Bt_h[NOUT * KTOT];   // [n][k] gamma-scaled fp16

// ---------------- helpers ----------------
__device__ __forceinline__ unsigned smem_u32(const void* p) {
    unsigned a;
    asm("{ .reg .u64 t; cvta.to.shared.u64 t, %1; cvt.u32.u64 %0, t; }" : "=r"(a) : "l"(p));
    return a;
}
__device__ __forceinline__ void ldsm4(unsigned& r0, unsigned& r1, unsigned& r2, unsigned& r3,
                                      unsigned addr) {
    asm volatile("ldmatrix.sync.aligned.m8n8.x4.shared.b16 {%0,%1,%2,%3}, [%4];"
                 : "=r"(r0), "=r"(r1), "=r"(r2), "=r"(r3) : "r"(addr));
}
__device__ __forceinline__ void mma_f16(float* c, const unsigned* a, unsigned b0, unsigned b1) {
    asm volatile(
        "mma.sync.aligned.m16n8k16.row.col.f32.f16.f16.f32 "
        "{%0,%1,%2,%3}, {%4,%5,%6,%7}, {%8,%9}, {%0,%1,%2,%3};"
        : "+f"(c[0]), "+f"(c[1]), "+f"(c[2]), "+f"(c[3])
        : "r"(a[0]), "r"(a[1]), "r"(a[2]), "r"(a[3]), "r"(b0), "r"(b1));
}
#define CP_ASYNC16(s, g) \
    asm volatile("cp.async.cg.shared.global [%0], [%1], 16;" :: "r"(s), "l"(g))
#define CP_COMMIT() asm volatile("cp.async.commit_group;")

// ---------------- prep kernels ----------------
__global__ __launch_bounds__(256)
void prep1(const float* __restrict__ w, const float* __restrict__ gamma,
           const float* __restrict__ beta) {
    __shared__ float ts[PREP_KROWS][NOUT + 1];
    __shared__ float gam_s[PREP_KROWS], bet_s[PREP_KROWS];
    const int tid = threadIdx.x;
    const int k0  = blockIdx.x * PREP_KROWS;

    if (tid < PREP_KROWS) {
        gam_s[tid] = gamma[k0 + tid];
        bet_s[tid] = beta[k0 + tid];
    }
    for (int i = tid; i < PREP_KROWS * NOUT; i += 256) {
        int r = i / NOUT, n = i - r * NOUT;
        ts[r][n] = w[(k0 + r) * NOUT + n];
    }
    __syncthreads();

    if (tid < NOUT) {
        float g = 0.f, c = 0.f;
        __half hbuf[PREP_KROWS];
#pragma unroll
        for (int r = 0; r < PREP_KROWS; ++r) {
            float wv = ts[r][tid];
            g += gam_s[r] * wv;
            c += bet_s[r] * wv;
            hbuf[r] = __float2half_rn(gam_s[r] * wv);
        }
        g_part_g[blockIdx.x * NOUT + tid] = g;
        g_part_c[blockIdx.x * NOUT + tid] = c;
        *(uint4*)(&g_Bt_h[tid * KTOT + k0]) = *(uint4*)hbuf;
    }
}

__global__ void prep2() {
    int o = threadIdx.x;   // 192 threads
    float g = 0.f, c = 0.f;
#pragma unroll 8
    for (int b = 0; b < PREP_BLKS; ++b) {
        g += g_part_g[b * NOUT + o];
        c += g_part_c[b * NOUT + o];
    }
    g_gv[o] = g;
    g_cv[o] = c;
}

// ---------------- main kernel ----------------
extern __shared__ __align__(16) unsigned char dsm[];

__global__ __launch_bounds__(256, 2)
void pm_kernel(const float* __restrict__ x, float* __restrict__ out) {
    __shared__ float red[512];
    __shared__ float mu_s[TM], rs_s[TM];
    __shared__ float gv_s[NOUT], cv_s[NOUT];

    const int tid = threadIdx.x, wid = tid >> 5, lane = tid & 31;
    const unsigned dbase = smem_u32(dsm);

    if (tid < NOUT) { gv_s[tid] = g_gv[tid]; cv_s[tid] = g_cv[tid]; }

    // gather mapping: thread (tl, kk0): token tl, 8 k's per tile (kk0*8..+7)
    const int tl  = tid & (TM - 1);
    const int kk0 = tid >> 6;
    const int t   = blockIdx.x * TM + tl;
    const int wx = t & 31, hy = (t >> 5) & 31, dz = (t >> 10) & 15, bb = t >> 14;
    const float* xb = x + bb * XS_B + (2 * dz) * XS_D + (2 * hy) * XS_H + 2 * wx;

    // warp GEMM tile: m32 x n48
    const int warpM = (wid & 1) * 32;
    const int warpN = (wid >> 1) * 48;

    float acc[2][6][4];
#pragma unroll
    for (int mi = 0; mi < 2; ++mi)
#pragma unroll
        for (int nj = 0; nj < 6; ++nj)
#pragma unroll
            for (int e = 0; e < 4; ++e) acc[mi][nj][e] = 0.f;

    float sum = 0.f, sq = 0.f;
    float v[8], stash[8];

    // prologue: gather tile kt=0 (octant p=0, c0=0) via float2; stash partner (p=1 -> tile 3)
#pragma unroll
    for (int i = 0; i < 8; ++i) {
        float2 xv = *(const float2*)(xb + (kk0 * 8 + i) * XS_C);
        v[i] = xv.x;
        stash[i] = xv.y;
    }
    // prefetch B tile 0 -> buf 0
#pragma unroll
    for (int j = 0; j < 3; ++j) {
        int idx = tid + 256 * j;
        int n = idx >> 2, ch = idx & 3;
        CP_ASYNC16(dbase + BH_OFF(0) + n * AROW + ch * 16,
                   (const char*)g_Bt_h + (long)n * (KTOT * 2) + ch * 16);
    }
    CP_COMMIT();

    // processed K-tile order per group of 6: 0,3,1,4,2,5 (+6g)
    for (int g = 0; g < 4; ++g) {
#pragma unroll
        for (int r = 0; r < 6; ++r) {
            const int buf = r & 1;
            const bool last = (g == 3) && (r == 5);
            // kperm[pos+1] - 6g:
            const int ktn_rel = (r < 5) ? ((r & 1) ? ((r + 1) >> 1) : ((r + 1) >> 1) + 3) : 6;
            __syncthreads();   // A smem + B[buf^1] free

            // prefetch next B tile
            if (!last) {
                const int ktn = g * 6 + ktn_rel;
#pragma unroll
                for (int j = 0; j < 3; ++j) {
                    int idx = tid + 256 * j;
                    int n = idx >> 2, ch = idx & 3;
                    CP_ASYNC16(dbase + BH_OFF(buf ^ 1) + n * AROW + ch * 16,
                               (const char*)g_Bt_h + (long)n * (KTOT * 2) + ktn * (KT * 2) + ch * 16);
                }
                CP_COMMIT();
            }

            // v -> fp16, store A tile, LN stats
            {
                unsigned hw[4];
#pragma unroll
                for (int i = 0; i < 4; ++i) {
                    float a = v[2 * i], b = v[2 * i + 1];
                    sum += a + b;
                    sq  += a * a + b * b;
                    __half ah = __float2half_rn(a), bh = __float2half_rn(b);
                    hw[i] = (unsigned)__half_as_ushort(ah) | ((unsigned)__half_as_ushort(bh) << 16);
                }
                unsigned rb = tl * AROW + kk0 * 16;
                *(uint4*)(dsm + AH_OFF + rb) = make_uint4(hw[0], hw[1], hw[2], hw[3]);
            }

            if (!last) { asm volatile("cp.async.wait_group 1;"); }
            else       { asm volatile("cp.async.wait_group 0;"); }
            __syncthreads();

            // ---- mma over this K-tile (single product) ----
            const unsigned bh_base = dbase + BH_OFF(buf);
#pragma unroll
            for (int ks = 0; ks < 2; ++ks) {
                unsigned a_h[2][4];
#pragma unroll
                for (int mi = 0; mi < 2; ++mi) {
                    unsigned row = warpM + mi * 16 + (lane & 15);
                    unsigned off = row * AROW + (ks * 2 + (lane >> 4)) * 16;
                    ldsm4(a_h[mi][0], a_h[mi][1], a_h[mi][2], a_h[mi][3], dbase + AH_OFF + off);
                }
#pragma unroll
                for (int j = 0; j < 3; ++j) {
                    unsigned brow = warpN + j * 16 + ((lane >> 4) << 3) + (lane & 7);
                    unsigned boff = brow * AROW + (ks * 2 + ((lane >> 3) & 1)) * 16;
                    unsigned b0, b1, b2, b3;
                    ldsm4(b0, b1, b2, b3, bh_base + boff);
#pragma unroll
                    for (int mi = 0; mi < 2; ++mi) {
                        mma_f16(acc[mi][j * 2],     a_h[mi], b0, b1);
                        mma_f16(acc[mi][j * 2 + 1], a_h[mi], b2, b3);
                    }
                }
            }

            // prepare v for next tile
            if (!last) {
                if ((r & 1) == 0) {
                    // next tile is the stashed odd-octant partner
#pragma unroll
                    for (int i = 0; i < 8; ++i) v[i] = stash[i];
                } else {
                    // next tile is even-octant: float2 load, stash partner
                    const int p  = (r == 5) ? 2 * g + 2 : 2 * g;
                    const int c0 = (r == 1) ? 32 : (r == 3) ? 64 : 0;
                    const int offs = (p >> 2) * XS_D + ((p >> 1) & 1) * XS_H;
#pragma unroll
                    for (int i = 0; i < 8; ++i) {
                        float2 xv = *(const float2*)(xb + (c0 + kk0 * 8 + i) * XS_C + offs);
                        v[i] = xv.x;
                        stash[i] = xv.y;
                    }
                }
            }
        }
    }

    // ---- LN stats reduction (4 partials per token) ----
    red[tid] = sum;
    red[tid + 256] = sq;
    __syncthreads();
    if (tid < TM) {
        float s  = red[tid] + red[tid + 64] + red[tid + 128] + red[tid + 192];
        float ss = red[tid + 256] + red[tid + 320] + red[tid + 384] + red[tid + 448];
        float mu  = s * (1.f / 768.f);
        float var = ss * (1.f / 768.f) - mu * mu;
        mu_s[tid] = mu;
        rs_s[tid] = rsqrtf(var + 1e-5f);
    }
    __syncthreads();

    // ---- epilogue: LN fold + transpose via smem, coalesced stores ----
    float* etile = (float*)dsm;   // [96][68] f32 = 26112 B
    const int T0 = blockIdx.x * TM;
    const int base0 = (T0 >> 14) * OS_B + ((T0 >> 10) & 15) * OS_D + ((T0 >> 5) & 31) * OS_H;
    const int lane4 = lane >> 2, lpair = (lane & 3) * 2;

#pragma unroll
    for (int ph = 0; ph < 2; ++ph) {
        if ((warpN / 96) == ph) {
            const int nb = warpN - ph * 96;
#pragma unroll
            for (int mi = 0; mi < 2; ++mi)
#pragma unroll
                for (int nj = 0; nj < 6; ++nj) {
                    int nloc = nb + nj * 8 + lpair;
                    int o = ph * 96 + nloc;
                    float g0 = gv_s[o], g1 = gv_s[o + 1];
                    float c0 = cv_s[o], c1 = cv_s[o + 1];
#pragma unroll
                    for (int e = 0; e < 2; ++e) {
                        int row = warpM + mi * 16 + lane4 + e * 8;
                        float mu = mu_s[row], rs = rs_s[row];
                        etile[nloc * 68 + row]       = rs * (acc[mi][nj][2 * e]     - mu * g0) + c0;
                        etile[(nloc + 1) * 68 + row] = rs * (acc[mi][nj][2 * e + 1] - mu * g1) + c1;
                    }
                }
        }
        __syncthreads();
#pragma unroll
        for (int j = 0; j < 24; ++j) {
            int idx = tid + 256 * j;
            int ol = idx >> 6, pos = idx & 63;
            out[base0 + (ph * 96 + ol) * OS_O + pos] = etile[ol * 68 + pos];
        }
        __syncthreads();
    }
}

extern "C" void kernel_launch(void* const* d_in, const int* in_sizes, int n_in,
                              void* d_out, int out_size) {
    const float* x     = (const float*)d_in[0];
    const float* gamma = (const float*)d_in[1];
    const float* beta  = (const float*)d_in[2];
    const float* w     = (const float*)d_in[3];
    float* out = (float*)d_out;

    cudaFuncSetAttribute(pm_kernel, cudaFuncAttributeMaxDynamicSharedMemorySize, DSMEM_BYTES);

    prep1<<<PREP_BLKS, 256>>>(w, gamma, beta);
    prep2<<<1, NOUT>>>();
    pm_kernel<<<32768 / TM, 256, DSMEM_BYTES>>>(x, out);
}